// round 9
// baseline (speedup 1.0000x reference)
#include <cuda_runtime.h>
#include <stdint.h>

#define THRESH   0.05f
#define SPEC     0.95f      // speculative cutoff; valid because hoi,ps,os < 1
#define TBITS    0x3F733333 // __float_as_uint(0.95f); int cmp == float cmp (pos floats)
#define NBINS    4096
#define CAP      65536
#define RANKMAX  4096

__device__ unsigned int g_bar;      // monotonic barrier counter (fallback only)
__device__ unsigned int g_done;     // monotonic last-out counter (k_rank)
__device__ unsigned int g_count;    // fast-path candidates (reset by last block out)
__device__ unsigned int g_count2;   // fallback candidates  (reset by last block out)
__device__ unsigned int g_hist[NBINS];
__device__ unsigned long long g_ck[CAP];    // packed keys, fast path
__device__ unsigned long long g_ck2[CAP];   // packed keys, fallback

// key packs (value, index) so that key_j > key_i  <=>  j ranks ahead of i
// (value desc, index asc — matches jax.lax.top_k). Values positive floats:
// uint compare == float compare. Keys unique (indices unique).
__device__ __forceinline__ unsigned long long mk_key(unsigned int vbits, unsigned int idx) {
    return ((unsigned long long)vbits << 32) | (unsigned long long)(0xFFFFFFFFu - idx);
}

// ---------------------------------------------------------------------------
// Kernel A: stream hoi once (issue-bound => minimize slots/byte).
// Group test: max-of-4 via DPX VIMNMX3 + IMNMX, one int compare vs TBITS.
// Slow path (~18.5% of groups): per-element exact v = h*ps*os > SPEC.
// ---------------------------------------------------------------------------
__device__ __forceinline__ void slow4(uint4 a, unsigned int e, unsigned long long magic,
                                      const float* __restrict__ ps,
                                      const float* __restrict__ os) {
    unsigned int hv[4] = {a.x, a.y, a.z, a.w};
    #pragma unroll
    for (int j = 0; j < 4; j++) {
        if ((int)hv[j] > TBITS) {
            unsigned int idx = e + (unsigned)j;
            unsigned int r = (unsigned int)(((unsigned long long)idx * magic) >> 33);
            float v = __uint_as_float(hv[j]) * ps[r] * os[r];
            if (v > SPEC) {
                unsigned int pos = atomicAdd(&g_count, 1u);
                if (pos < CAP)
                    g_ck[pos] = mk_key(__float_as_uint(v), idx);
            }
        }
    }
}

__device__ __forceinline__ int max4i(uint4 a) {
    int m = __vimax3_s32((int)a.x, (int)a.y, (int)a.z);
    return max(m, (int)a.w);
}

__global__ void __launch_bounds__(256)
k_scan(const uint4* __restrict__ hoi4,
       const float* __restrict__ ps,
       const float* __restrict__ os,
       unsigned int nvec, unsigned int N, unsigned long long magic) {
    unsigned int stride = gridDim.x * blockDim.x;
    unsigned int q = blockIdx.x * blockDim.x + threadIdx.x;
    // 8 independent LDG.128 per iteration (front-batched -> MLP 8)
    for (; q + 7u * stride < nvec; q += 8u * stride) {
        uint4 h[8];
        #pragma unroll
        for (int t = 0; t < 8; t++) h[t] = __ldcs(hoi4 + q + (unsigned)t * stride);
        #pragma unroll
        for (int t = 0; t < 8; t++) {
            if (max4i(h[t]) > TBITS)
                slow4(h[t], (q + (unsigned)t * stride) * 4u, magic, ps, os);
        }
    }
    for (; q < nvec; q += stride) {
        uint4 h = __ldcs(hoi4 + q);
        if (max4i(h) > TBITS)
            slow4(h, q * 4u, magic, ps, os);
    }
    if (blockIdx.x == 0 && threadIdx.x == 0) {
        for (unsigned int e = nvec * 4u; e < N; e++) {
            unsigned int hb = ((const unsigned int*)hoi4)[e];
            if ((int)hb > TBITS) {
                unsigned int r = (unsigned int)(((unsigned long long)e * magic) >> 33);
                float v = __uint_as_float(hb) * ps[r] * os[r];
                if (v > SPEC) {
                    unsigned int pos = atomicAdd(&g_count, 1u);
                    if (pos < CAP) g_ck[pos] = mk_key(__float_as_uint(v), e);
                }
            }
        }
    }
}

// ---------------------------------------------------------------------------
// Write one ranked detection into the flat output:
//   [0,T) scores | [T,5T) pboxes | [5T,9T) oboxes | [9T,10T) ocls
//   [10T,11T) action | [11T,12T) valid
// ---------------------------------------------------------------------------
__device__ __forceinline__ void write_det(unsigned int rank, unsigned long long kb,
                                          const float4* __restrict__ pb,
                                          const float4* __restrict__ ob,
                                          const int* __restrict__ ocls,
                                          float* __restrict__ out,
                                          unsigned int K, int T,
                                          unsigned long long magic) {
    unsigned int vb = (unsigned int)(kb >> 32);
    unsigned int ix = 0xFFFFFFFFu - (unsigned int)(kb & 0xFFFFFFFFu);
    unsigned int pair = (unsigned int)(((unsigned long long)ix * magic) >> 33);
    unsigned int act  = ix - pair * K;
    out[rank] = __uint_as_float(vb);
    float4 p = pb[pair];
    float4 o = ob[pair];
    out[T + 4 * rank + 0] = p.x;  out[T + 4 * rank + 1] = p.y;
    out[T + 4 * rank + 2] = p.z;  out[T + 4 * rank + 3] = p.w;
    out[5 * T + 4 * rank + 0] = o.x;  out[5 * T + 4 * rank + 1] = o.y;
    out[5 * T + 4 * rank + 2] = o.z;  out[5 * T + 4 * rank + 3] = o.w;
    out[9 * T + rank]  = (float)ocls[pair];
    out[10 * T + rank] = (float)act;
    out[11 * T + rank] = 1.0f;
}

// Warp-parallel exact rank+write over packed keys in global memory.
// Each warp takes one item; lanes partition j-space (unrolled x4 LDG.64).
__device__ __forceinline__ void warp_rank_write(const unsigned long long* __restrict__ keys,
                                                unsigned int n,
                                                const float4* __restrict__ pb,
                                                const float4* __restrict__ ob,
                                                const int* __restrict__ ocls,
                                                float* __restrict__ out,
                                                unsigned int K, int T,
                                                unsigned long long magic) {
    unsigned int nwarps = (gridDim.x * blockDim.x) >> 5;
    unsigned int gw = (blockIdx.x * blockDim.x + threadIdx.x) >> 5;
    unsigned int lane = threadIdx.x & 31u;
    for (unsigned int i = gw; i < n; i += nwarps) {
        unsigned long long kb = keys[i];
        unsigned int cnt = 0;
        unsigned int jb = 0;
        for (; jb + 128u <= n; jb += 128u) {
            unsigned int a = 0;
            #pragma unroll
            for (int t = 0; t < 4; t++)
                a += (keys[jb + (unsigned)t * 32u + lane] > kb);
            cnt += a;
        }
        for (; jb < n; jb += 32u) {
            unsigned int j = jb + lane;
            if (j < n) cnt += (keys[j] > kb);
        }
        cnt = __reduce_add_sync(0xFFFFFFFFu, cnt);
        if (lane == 0 && cnt < (unsigned int)T)
            write_det(cnt, kb, pb, ob, ocls, out, K, T, magic);
    }
}

// Grid barrier for the (never-taken) fallback path only.
__device__ __forceinline__ void grid_barrier(unsigned int nblocks) {
    __syncthreads();
    __threadfence();
    if (threadIdx.x == 0) {
        unsigned int old = atomicAdd(&g_bar, 1u);
        unsigned int target = (old / nblocks + 1u) * nblocks;
        while (atomicAdd(&g_bar, 0u) < target) __nanosleep(256);
    }
    __syncthreads();
}

// ---------------------------------------------------------------------------
// Kernel B: fast path = warp-per-item parallel rank straight from global keys.
// Fallback = exact hist -> cutoff -> collect -> rank.
// Counter reset: last-block-out on monotonic g_done.
// ---------------------------------------------------------------------------
__global__ void __launch_bounds__(256)
k_rank(const float4* __restrict__ hoi4,
       const float*  __restrict__ ps, const float* __restrict__ os,
       const float4* __restrict__ pb, const float4* __restrict__ ob,
       const int*    __restrict__ ocls, float* __restrict__ out,
       unsigned int nvec, unsigned int N, unsigned int K,
       unsigned long long magic, int T, unsigned int nblocks) {
    unsigned int n = *(volatile unsigned int*)&g_count;   // uniform across blocks
    bool fast = (n >= (unsigned int)T && n <= RANKMAX);

    if (fast) {
        warp_rank_write(g_ck, n, pb, ob, ocls, out, K, T, magic);
    } else {
        // ===== exact fallback (all blocks take this branch uniformly) =====
        __shared__ unsigned int sh[NBINS];
        {   // zero global hist
            unsigned int stride = gridDim.x * blockDim.x;
            for (unsigned int i = blockIdx.x * blockDim.x + threadIdx.x; i < NBINS; i += stride)
                g_hist[i] = 0;
        }
        grid_barrier(nblocks);

        {   // shared-privatized histogram of v > THRESH
            for (int i = threadIdx.x; i < NBINS; i += blockDim.x) sh[i] = 0;
            __syncthreads();
            unsigned int stride = gridDim.x * blockDim.x;
            for (unsigned int q = blockIdx.x * blockDim.x + threadIdx.x; q < nvec; q += stride) {
                float4 h = hoi4[q];
                unsigned int e = q * 4u;
                float hv[4] = {h.x, h.y, h.z, h.w};
                #pragma unroll
                for (int j = 0; j < 4; j++) {
                    unsigned int idx = e + (unsigned)j;
                    unsigned int r = (unsigned int)(((unsigned long long)idx * magic) >> 33);
                    float v = hv[j] * ps[r] * os[r];
                    if (v > THRESH) {
                        unsigned int b = (unsigned int)(v * (float)NBINS);
                        if (b > NBINS - 1) b = NBINS - 1;
                        atomicAdd(&sh[b], 1u);
                    }
                }
            }
            if (blockIdx.x == 0 && threadIdx.x == 0) {
                for (unsigned int e = nvec * 4u; e < N; e++) {
                    unsigned int r = (unsigned int)(((unsigned long long)e * magic) >> 33);
                    float v = ((const float*)hoi4)[e] * ps[r] * os[r];
                    if (v > THRESH) {
                        unsigned int b = (unsigned int)(v * (float)NBINS);
                        if (b > NBINS - 1) b = NBINS - 1;
                        atomicAdd(&sh[b], 1u);
                    }
                }
            }
            __syncthreads();
            for (int i = threadIdx.x; i < NBINS; i += blockDim.x)
                if (sh[i]) atomicAdd(&g_hist[i], sh[i]);
        }
        grid_barrier(nblocks);

        __shared__ unsigned int s_cut;
        if (threadIdx.x == 0) {
            unsigned int cum = 0, cut = 0;
            for (int b = NBINS - 1; b >= 0; b--) {
                cum += g_hist[b];
                if (cum >= (unsigned int)T) { cut = (unsigned int)b; break; }
            }
            s_cut = cut;
        }
        __syncthreads();
        unsigned int cut = s_cut;

        {   // collect candidates with bin >= cutoff (packed keys)
            unsigned int stride = gridDim.x * blockDim.x;
            for (unsigned int q = blockIdx.x * blockDim.x + threadIdx.x; q < nvec; q += stride) {
                float4 h = hoi4[q];
                unsigned int e = q * 4u;
                float hv[4] = {h.x, h.y, h.z, h.w};
                #pragma unroll
                for (int j = 0; j < 4; j++) {
                    unsigned int idx = e + (unsigned)j;
                    unsigned int r = (unsigned int)(((unsigned long long)idx * magic) >> 33);
                    float v = hv[j] * ps[r] * os[r];
                    if (v > THRESH) {
                        unsigned int b = (unsigned int)(v * (float)NBINS);
                        if (b > NBINS - 1) b = NBINS - 1;
                        if (b >= cut) {
                            unsigned int pos = atomicAdd(&g_count2, 1u);
                            if (pos < CAP)
                                g_ck2[pos] = mk_key(__float_as_uint(v), idx);
                        }
                    }
                }
            }
            if (blockIdx.x == 0 && threadIdx.x == 0) {
                for (unsigned int e = nvec * 4u; e < N; e++) {
                    unsigned int r = (unsigned int)(((unsigned long long)e * magic) >> 33);
                    float v = ((const float*)hoi4)[e] * ps[r] * os[r];
                    if (v > THRESH) {
                        unsigned int b = (unsigned int)(v * (float)NBINS);
                        if (b > NBINS - 1) b = NBINS - 1;
                        if (b >= cut) {
                            unsigned int pos = atomicAdd(&g_count2, 1u);
                            if (pos < CAP)
                                g_ck2[pos] = mk_key(__float_as_uint(v), e);
                        }
                    }
                }
            }
        }
        grid_barrier(nblocks);

        unsigned int n2 = *(volatile unsigned int*)&g_count2;
        if (n2 > CAP) n2 = CAP;
        warp_rank_write(g_ck2, n2, pb, ob, ocls, out, K, T, magic);

        // zero-pad unfilled slots (n2 < T): block 0
        if (blockIdx.x == 0) {
            for (int s = threadIdx.x; s < T; s += blockDim.x) {
                if ((unsigned int)s >= n2) {
                    out[s] = 0.0f;
                    #pragma unroll
                    for (int d = 0; d < 4; d++) {
                        out[T + 4 * s + d] = 0.0f;
                        out[5 * T + 4 * s + d] = 0.0f;
                    }
                    out[9 * T + s] = 0.0f;
                    out[10 * T + s] = 0.0f;
                    out[11 * T + s] = 0.0f;
                }
            }
        }
    }

    // ---- last-block-out counter reset (race-free: every block's read of
    // g_count precedes its arrival; reset fires only at the final arrival) ----
    __syncthreads();
    __threadfence();
    if (threadIdx.x == 0) {
        unsigned int old = atomicAdd(&g_done, 1u);
        if ((old % nblocks) == nblocks - 1u) {
            g_count = 0;
            g_count2 = 0;
        }
    }
}

// ---------------------------------------------------------------------------
extern "C" void kernel_launch(void* const* d_in, const int* in_sizes, int n_in,
                              void* d_out, int out_size) {
    const float* pb   = (const float*)d_in[0];
    const float* ob   = (const float*)d_in[1];
    const float* ps   = (const float*)d_in[2];
    const float* os   = (const float*)d_in[3];
    const int*   ocls = (const int*)d_in[4];
    const float* hoi  = (const float*)d_in[5];

    int R = in_sizes[2];
    unsigned int N = (unsigned int)in_sizes[5];
    unsigned int K = N / (unsigned int)R;
    int T = out_size / 12;
    unsigned int nvec = N / 4u;
    unsigned long long magic = ((1ULL << 33) + K - 1) / K;  // exact e/K, e < 2^33/K

    int dev = 0, sms = 148;
    cudaGetDevice(&dev);
    cudaDeviceGetAttribute(&sms, cudaDevAttrMultiProcessorCount, dev);

    unsigned int scan_blocks = (unsigned int)(sms * 8);
    k_scan<<<scan_blocks, 256>>>((const uint4*)hoi, ps, os, nvec, N, magic);

    unsigned int fb_blocks = (unsigned int)sms;   // co-resident for fallback barrier
    k_rank<<<fb_blocks, 256>>>((const float4*)hoi, ps, os,
                               (const float4*)pb, (const float4*)ob, ocls,
                               (float*)d_out, nvec, N, K, magic, T, fb_blocks);
}

// round 10
// speedup vs baseline: 1.0556x; 1.0556x over previous
#include <cuda_runtime.h>
#include <stdint.h>

#define THRESH   0.05f
#define SPEC     0.95f      // speculative cutoff; valid because hoi,ps,os < 1
#define NBINS    4096
#define CAP      65536
#define RANKMAX  4096

__device__ unsigned int g_bar;      // monotonic barrier counter (fallback only)
__device__ unsigned int g_done;     // monotonic last-out counter (k_rank)
__device__ unsigned int g_count;    // fast-path candidates (reset by last block out)
__device__ unsigned int g_count2;   // fallback candidates  (reset by last block out)
__device__ unsigned int g_hist[NBINS];
__device__ unsigned long long g_ck[CAP];    // packed keys, fast path
__device__ unsigned long long g_ck2[CAP];   // packed keys, fallback

// key packs (value, index) so that key_j > key_i  <=>  j ranks ahead of i
// (value desc, index asc — matches jax.lax.top_k). Values positive floats:
// uint compare == float compare. Keys unique (indices unique).
__device__ __forceinline__ unsigned long long mk_key(unsigned int vbits, unsigned int idx) {
    return ((unsigned long long)vbits << 32) | (unsigned long long)(0xFFFFFFFFu - idx);
}

// ---------------------------------------------------------------------------
// Kernel A: stream hoi once. Stage-1 filter h > SPEC (free: v = h*ps*os <= h).
// Stage-2 (~5% of elements): exact v > SPEC test with the two scalar loads.
// Default cache policy (no __ldcs): hoi ~fits in L2, so graph replays can
// re-hit L2 under pseudo-random replacement.
// ---------------------------------------------------------------------------
__device__ __forceinline__ void scan4(float4 h, unsigned int e, unsigned long long magic,
                                      const float* __restrict__ ps,
                                      const float* __restrict__ os) {
    float m = fmaxf(fmaxf(h.x, h.y), fmaxf(h.z, h.w));
    if (m > SPEC) {
        float hv[4] = {h.x, h.y, h.z, h.w};
        #pragma unroll
        for (int j = 0; j < 4; j++) {
            if (hv[j] > SPEC) {
                unsigned int idx = e + (unsigned)j;
                unsigned int r = (unsigned int)(((unsigned long long)idx * magic) >> 33);
                float v = hv[j] * ps[r] * os[r];
                if (v > SPEC) {
                    unsigned int pos = atomicAdd(&g_count, 1u);
                    if (pos < CAP)
                        g_ck[pos] = mk_key(__float_as_uint(v), idx);
                }
            }
        }
    }
}

__global__ void __launch_bounds__(256)
k_scan(const float4* __restrict__ hoi4,
       const float*  __restrict__ ps,
       const float*  __restrict__ os,
       unsigned int nvec, unsigned int N, unsigned long long magic) {
    unsigned int stride = gridDim.x * blockDim.x;
    unsigned int q = blockIdx.x * blockDim.x + threadIdx.x;
    for (; q + 3u * stride < nvec; q += 4u * stride) {
        float4 h0 = hoi4[q];
        float4 h1 = hoi4[q + stride];
        float4 h2 = hoi4[q + 2u * stride];
        float4 h3 = hoi4[q + 3u * stride];
        scan4(h0, q * 4u, magic, ps, os);
        scan4(h1, (q + stride) * 4u, magic, ps, os);
        scan4(h2, (q + 2u * stride) * 4u, magic, ps, os);
        scan4(h3, (q + 3u * stride) * 4u, magic, ps, os);
    }
    for (; q < nvec; q += stride) {
        float4 h = hoi4[q];
        scan4(h, q * 4u, magic, ps, os);
    }
    if (blockIdx.x == 0 && threadIdx.x == 0) {
        for (unsigned int e = nvec * 4u; e < N; e++) {
            float h = ((const float*)hoi4)[e];
            if (h > SPEC) {
                unsigned int r = (unsigned int)(((unsigned long long)e * magic) >> 33);
                float v = h * ps[r] * os[r];
                if (v > SPEC) {
                    unsigned int pos = atomicAdd(&g_count, 1u);
                    if (pos < CAP) g_ck[pos] = mk_key(__float_as_uint(v), e);
                }
            }
        }
    }
}

// ---------------------------------------------------------------------------
// Write one ranked detection into the flat output:
//   [0,T) scores | [T,5T) pboxes | [5T,9T) oboxes | [9T,10T) ocls
//   [10T,11T) action | [11T,12T) valid
// ---------------------------------------------------------------------------
__device__ __forceinline__ void write_det(unsigned int rank, unsigned long long kb,
                                          const float4* __restrict__ pb,
                                          const float4* __restrict__ ob,
                                          const int* __restrict__ ocls,
                                          float* __restrict__ out,
                                          unsigned int K, int T,
                                          unsigned long long magic) {
    unsigned int vb = (unsigned int)(kb >> 32);
    unsigned int ix = 0xFFFFFFFFu - (unsigned int)(kb & 0xFFFFFFFFu);
    unsigned int pair = (unsigned int)(((unsigned long long)ix * magic) >> 33);
    unsigned int act  = ix - pair * K;
    out[rank] = __uint_as_float(vb);
    float4 p = pb[pair];
    float4 o = ob[pair];
    out[T + 4 * rank + 0] = p.x;  out[T + 4 * rank + 1] = p.y;
    out[T + 4 * rank + 2] = p.z;  out[T + 4 * rank + 3] = p.w;
    out[5 * T + 4 * rank + 0] = o.x;  out[5 * T + 4 * rank + 1] = o.y;
    out[5 * T + 4 * rank + 2] = o.z;  out[5 * T + 4 * rank + 3] = o.w;
    out[9 * T + rank]  = (float)ocls[pair];
    out[10 * T + rank] = (float)act;
    out[11 * T + rank] = 1.0f;
}

// Warp-parallel exact rank+write over packed keys in global memory.
// Each warp takes one item; lanes partition j-space (unrolled x4 LDG.64).
__device__ __forceinline__ void warp_rank_write(const unsigned long long* __restrict__ keys,
                                                unsigned int n,
                                                const float4* __restrict__ pb,
                                                const float4* __restrict__ ob,
                                                const int* __restrict__ ocls,
                                                float* __restrict__ out,
                                                unsigned int K, int T,
                                                unsigned long long magic) {
    unsigned int nwarps = (gridDim.x * blockDim.x) >> 5;
    unsigned int gw = (blockIdx.x * blockDim.x + threadIdx.x) >> 5;
    unsigned int lane = threadIdx.x & 31u;
    for (unsigned int i = gw; i < n; i += nwarps) {
        unsigned long long kb = keys[i];
        unsigned int cnt = 0;
        unsigned int jb = 0;
        for (; jb + 128u <= n; jb += 128u) {
            unsigned int a = 0;
            #pragma unroll
            for (int t = 0; t < 4; t++)
                a += (keys[jb + (unsigned)t * 32u + lane] > kb);
            cnt += a;
        }
        for (; jb < n; jb += 32u) {
            unsigned int j = jb + lane;
            if (j < n) cnt += (keys[j] > kb);
        }
        cnt = __reduce_add_sync(0xFFFFFFFFu, cnt);
        if (lane == 0 && cnt < (unsigned int)T)
            write_det(cnt, kb, pb, ob, ocls, out, K, T, magic);
    }
}

// Grid barrier for the (never-taken) fallback path only.
__device__ __forceinline__ void grid_barrier(unsigned int nblocks) {
    __syncthreads();
    __threadfence();
    if (threadIdx.x == 0) {
        unsigned int old = atomicAdd(&g_bar, 1u);
        unsigned int target = (old / nblocks + 1u) * nblocks;
        while (atomicAdd(&g_bar, 0u) < target) __nanosleep(256);
    }
    __syncthreads();
}

// ---------------------------------------------------------------------------
// Kernel B: fast path = warp-per-item parallel rank straight from global keys.
// Fallback = exact hist -> cutoff -> collect -> rank.
// Counter reset: last-block-out on monotonic g_done.
// ---------------------------------------------------------------------------
__global__ void __launch_bounds__(256)
k_rank(const float4* __restrict__ hoi4,
       const float*  __restrict__ ps, const float* __restrict__ os,
       const float4* __restrict__ pb, const float4* __restrict__ ob,
       const int*    __restrict__ ocls, float* __restrict__ out,
       unsigned int nvec, unsigned int N, unsigned int K,
       unsigned long long magic, int T, unsigned int nblocks) {
    unsigned int n = *(volatile unsigned int*)&g_count;   // uniform across blocks
    bool fast = (n >= (unsigned int)T && n <= RANKMAX);

    if (fast) {
        warp_rank_write(g_ck, n, pb, ob, ocls, out, K, T, magic);
    } else {
        // ===== exact fallback (all blocks take this branch uniformly) =====
        __shared__ unsigned int sh[NBINS];
        {   // zero global hist
            unsigned int stride = gridDim.x * blockDim.x;
            for (unsigned int i = blockIdx.x * blockDim.x + threadIdx.x; i < NBINS; i += stride)
                g_hist[i] = 0;
        }
        grid_barrier(nblocks);

        {   // shared-privatized histogram of v > THRESH
            for (int i = threadIdx.x; i < NBINS; i += blockDim.x) sh[i] = 0;
            __syncthreads();
            unsigned int stride = gridDim.x * blockDim.x;
            for (unsigned int q = blockIdx.x * blockDim.x + threadIdx.x; q < nvec; q += stride) {
                float4 h = hoi4[q];
                unsigned int e = q * 4u;
                float hv[4] = {h.x, h.y, h.z, h.w};
                #pragma unroll
                for (int j = 0; j < 4; j++) {
                    unsigned int idx = e + (unsigned)j;
                    unsigned int r = (unsigned int)(((unsigned long long)idx * magic) >> 33);
                    float v = hv[j] * ps[r] * os[r];
                    if (v > THRESH) {
                        unsigned int b = (unsigned int)(v * (float)NBINS);
                        if (b > NBINS - 1) b = NBINS - 1;
                        atomicAdd(&sh[b], 1u);
                    }
                }
            }
            if (blockIdx.x == 0 && threadIdx.x == 0) {
                for (unsigned int e = nvec * 4u; e < N; e++) {
                    unsigned int r = (unsigned int)(((unsigned long long)e * magic) >> 33);
                    float v = ((const float*)hoi4)[e] * ps[r] * os[r];
                    if (v > THRESH) {
                        unsigned int b = (unsigned int)(v * (float)NBINS);
                        if (b > NBINS - 1) b = NBINS - 1;
                        atomicAdd(&sh[b], 1u);
                    }
                }
            }
            __syncthreads();
            for (int i = threadIdx.x; i < NBINS; i += blockDim.x)
                if (sh[i]) atomicAdd(&g_hist[i], sh[i]);
        }
        grid_barrier(nblocks);

        __shared__ unsigned int s_cut;
        if (threadIdx.x == 0) {
            unsigned int cum = 0, cut = 0;
            for (int b = NBINS - 1; b >= 0; b--) {
                cum += g_hist[b];
                if (cum >= (unsigned int)T) { cut = (unsigned int)b; break; }
            }
            s_cut = cut;
        }
        __syncthreads();
        unsigned int cut = s_cut;

        {   // collect candidates with bin >= cutoff (packed keys)
            unsigned int stride = gridDim.x * blockDim.x;
            for (unsigned int q = blockIdx.x * blockDim.x + threadIdx.x; q < nvec; q += stride) {
                float4 h = hoi4[q];
                unsigned int e = q * 4u;
                float hv[4] = {h.x, h.y, h.z, h.w};
                #pragma unroll
                for (int j = 0; j < 4; j++) {
                    unsigned int idx = e + (unsigned)j;
                    unsigned int r = (unsigned int)(((unsigned long long)idx * magic) >> 33);
                    float v = hv[j] * ps[r] * os[r];
                    if (v > THRESH) {
                        unsigned int b = (unsigned int)(v * (float)NBINS);
                        if (b > NBINS - 1) b = NBINS - 1;
                        if (b >= cut) {
                            unsigned int pos = atomicAdd(&g_count2, 1u);
                            if (pos < CAP)
                                g_ck2[pos] = mk_key(__float_as_uint(v), idx);
                        }
                    }
                }
            }
            if (blockIdx.x == 0 && threadIdx.x == 0) {
                for (unsigned int e = nvec * 4u; e < N; e++) {
                    unsigned int r = (unsigned int)(((unsigned long long)e * magic) >> 33);
                    float v = ((const float*)hoi4)[e] * ps[r] * os[r];
                    if (v > THRESH) {
                        unsigned int b = (unsigned int)(v * (float)NBINS);
                        if (b > NBINS - 1) b = NBINS - 1;
                        if (b >= cut) {
                            unsigned int pos = atomicAdd(&g_count2, 1u);
                            if (pos < CAP)
                                g_ck2[pos] = mk_key(__float_as_uint(v), e);
                        }
                    }
                }
            }
        }
        grid_barrier(nblocks);

        unsigned int n2 = *(volatile unsigned int*)&g_count2;
        if (n2 > CAP) n2 = CAP;
        warp_rank_write(g_ck2, n2, pb, ob, ocls, out, K, T, magic);

        // zero-pad unfilled slots (n2 < T): block 0
        if (blockIdx.x == 0) {
            for (int s = threadIdx.x; s < T; s += blockDim.x) {
                if ((unsigned int)s >= n2) {
                    out[s] = 0.0f;
                    #pragma unroll
                    for (int d = 0; d < 4; d++) {
                        out[T + 4 * s + d] = 0.0f;
                        out[5 * T + 4 * s + d] = 0.0f;
                    }
                    out[9 * T + s] = 0.0f;
                    out[10 * T + s] = 0.0f;
                    out[11 * T + s] = 0.0f;
                }
            }
        }
    }

    // ---- last-block-out counter reset (race-free: every block's read of
    // g_count precedes its arrival; reset fires only at the final arrival) ----
    __syncthreads();
    __threadfence();
    if (threadIdx.x == 0) {
        unsigned int old = atomicAdd(&g_done, 1u);
        if ((old % nblocks) == nblocks - 1u) {
            g_count = 0;
            g_count2 = 0;
        }
    }
}

// ---------------------------------------------------------------------------
extern "C" void kernel_launch(void* const* d_in, const int* in_sizes, int n_in,
                              void* d_out, int out_size) {
    const float* pb   = (const float*)d_in[0];
    const float* ob   = (const float*)d_in[1];
    const float* ps   = (const float*)d_in[2];
    const float* os   = (const float*)d_in[3];
    const int*   ocls = (const int*)d_in[4];
    const float* hoi  = (const float*)d_in[5];

    int R = in_sizes[2];
    unsigned int N = (unsigned int)in_sizes[5];
    unsigned int K = N / (unsigned int)R;
    int T = out_size / 12;
    unsigned int nvec = N / 4u;
    unsigned long long magic = ((1ULL << 33) + K - 1) / K;  // exact e/K, e < 2^33/K

    int dev = 0, sms = 148;
    cudaGetDevice(&dev);
    cudaDeviceGetAttribute(&sms, cudaDevAttrMultiProcessorCount, dev);

    unsigned int scan_blocks = (unsigned int)(sms * 8);
    k_scan<<<scan_blocks, 256>>>((const float4*)hoi, ps, os, nvec, N, magic);

    unsigned int fb_blocks = (unsigned int)sms;   // co-resident for fallback barrier
    k_rank<<<fb_blocks, 256>>>((const float4*)hoi, ps, os,
                               (const float4*)pb, (const float4*)ob, ocls,
                               (float*)d_out, nvec, N, K, magic, T, fb_blocks);
}

// round 11
// speedup vs baseline: 1.4021x; 1.3282x over previous
#include <cuda_runtime.h>
#include <stdint.h>

#define THRESH   0.05f
#define SPEC     0.95f      // speculative cutoff; valid because hoi,ps,os < 1
#define NBINS    4096
#define CAP      65536
#define RANKMAX  4096

__device__ unsigned int g_bar;      // monotonic barrier counter (fallback only)
__device__ unsigned int g_done;     // monotonic last-out counter (k_rank)
__device__ unsigned int g_count;    // fast-path candidates
__device__ unsigned int g_count2;   // fallback candidates
__device__ unsigned int g_hist[NBINS];
__device__ unsigned long long g_ck[CAP];    // packed keys, fast path
__device__ unsigned long long g_ck2[CAP];   // packed keys, fallback

// key packs (value, index) so that key_j > key_i  <=>  j ranks ahead of i
// (value desc, index asc — matches jax.lax.top_k). Values positive floats:
// uint compare == float compare. Keys unique (indices unique).
__device__ __forceinline__ unsigned long long mk_key(unsigned int vbits, unsigned int idx) {
    return ((unsigned long long)vbits << 32) | (unsigned long long)(0xFFFFFFFFu - idx);
}

__device__ __forceinline__ void push_fast(float v, unsigned int idx) {
    unsigned int pos = atomicAdd(&g_count, 1u);
    if (pos < CAP) g_ck[pos] = mk_key(__float_as_uint(v), idx);
}

// ---------------------------------------------------------------------------
// Kernel A: stream hoi once. Stage-1: group max > SPEC (free: v = h*ps*os <= h).
// Slow region (ONE divergent region per group): group-level r/c/bs computation,
// branch-free selects, predicated pushes (2.2e-5/element taken).
// ---------------------------------------------------------------------------
__device__ __forceinline__ void scan4(float4 h, unsigned int e, unsigned long long magic,
                                      const float* __restrict__ ps,
                                      const float* __restrict__ os,
                                      unsigned int K) {
    float m = fmaxf(fmaxf(h.x, h.y), fmaxf(h.z, h.w));
    if (m > SPEC) {
        unsigned int r = (unsigned int)(((unsigned long long)e * magic) >> 33);
        unsigned int c = e - r * K;
        float bs0 = ps[r] * os[r];
        float bs1 = bs0;
        if (c + 3 >= K) bs1 = ps[r + 1] * os[r + 1];   // ~2.6% of groups
        float v0 = h.x * bs0;
        float v1 = h.y * ((c + 1 < K) ? bs0 : bs1);
        float v2 = h.z * ((c + 2 < K) ? bs0 : bs1);
        float v3 = h.w * ((c + 3 < K) ? bs0 : bs1);
        if (v0 > SPEC) push_fast(v0, e);
        if (v1 > SPEC) push_fast(v1, e + 1);
        if (v2 > SPEC) push_fast(v2, e + 2);
        if (v3 > SPEC) push_fast(v3, e + 3);
    }
}

__global__ void __launch_bounds__(256)
k_scan(const float4* __restrict__ hoi4,
       const float*  __restrict__ ps,
       const float*  __restrict__ os,
       unsigned int nvec, unsigned int N, unsigned int K, unsigned long long magic) {
    unsigned int stride = gridDim.x * blockDim.x;
    unsigned int q = blockIdx.x * blockDim.x + threadIdx.x;
    for (; q + 3u * stride < nvec; q += 4u * stride) {
        float4 h0 = __ldcs(hoi4 + q);
        float4 h1 = __ldcs(hoi4 + q + stride);
        float4 h2 = __ldcs(hoi4 + q + 2u * stride);
        float4 h3 = __ldcs(hoi4 + q + 3u * stride);
        scan4(h0, q * 4u, magic, ps, os, K);
        scan4(h1, (q + stride) * 4u, magic, ps, os, K);
        scan4(h2, (q + 2u * stride) * 4u, magic, ps, os, K);
        scan4(h3, (q + 3u * stride) * 4u, magic, ps, os, K);
    }
    for (; q < nvec; q += stride) {
        float4 h = __ldcs(hoi4 + q);
        scan4(h, q * 4u, magic, ps, os, K);
    }
    if (blockIdx.x == 0 && threadIdx.x == 0) {
        for (unsigned int e = nvec * 4u; e < N; e++) {
            float h = ((const float*)hoi4)[e];
            if (h > SPEC) {
                unsigned int r = (unsigned int)(((unsigned long long)e * magic) >> 33);
                float v = h * ps[r] * os[r];
                if (v > SPEC) push_fast(v, e);
            }
        }
    }
}

// ---------------------------------------------------------------------------
// Write one ranked detection into the flat output:
//   [0,T) scores | [T,5T) pboxes | [5T,9T) oboxes | [9T,10T) ocls
//   [10T,11T) action | [11T,12T) valid
// ---------------------------------------------------------------------------
__device__ __forceinline__ void write_det(unsigned int rank, unsigned long long kb,
                                          const float4* __restrict__ pb,
                                          const float4* __restrict__ ob,
                                          const int* __restrict__ ocls,
                                          float* __restrict__ out,
                                          unsigned int K, int T,
                                          unsigned long long magic) {
    unsigned int vb = (unsigned int)(kb >> 32);
    unsigned int ix = 0xFFFFFFFFu - (unsigned int)(kb & 0xFFFFFFFFu);
    unsigned int pair = (unsigned int)(((unsigned long long)ix * magic) >> 33);
    unsigned int act  = ix - pair * K;
    out[rank] = __uint_as_float(vb);
    float4 p = pb[pair];
    float4 o = ob[pair];
    out[T + 4 * rank + 0] = p.x;  out[T + 4 * rank + 1] = p.y;
    out[T + 4 * rank + 2] = p.z;  out[T + 4 * rank + 3] = p.w;
    out[5 * T + 4 * rank + 0] = o.x;  out[5 * T + 4 * rank + 1] = o.y;
    out[5 * T + 4 * rank + 2] = o.z;  out[5 * T + 4 * rank + 3] = o.w;
    out[9 * T + rank]  = (float)ocls[pair];
    out[10 * T + rank] = (float)act;
    out[11 * T + rank] = 1.0f;
}

// Warp-parallel exact rank+write over packed keys in global memory.
__device__ __forceinline__ void warp_rank_write(const unsigned long long* __restrict__ keys,
                                                unsigned int n,
                                                const float4* __restrict__ pb,
                                                const float4* __restrict__ ob,
                                                const int* __restrict__ ocls,
                                                float* __restrict__ out,
                                                unsigned int K, int T,
                                                unsigned long long magic) {
    unsigned int nwarps = (gridDim.x * blockDim.x) >> 5;
    unsigned int gw = (blockIdx.x * blockDim.x + threadIdx.x) >> 5;
    unsigned int lane = threadIdx.x & 31u;
    for (unsigned int i = gw; i < n; i += nwarps) {
        unsigned long long kb = keys[i];
        unsigned int cnt = 0;
        unsigned int jb = 0;
        for (; jb + 128u <= n; jb += 128u) {
            unsigned int a = 0;
            #pragma unroll
            for (int t = 0; t < 4; t++)
                a += (keys[jb + (unsigned)t * 32u + lane] > kb);
            cnt += a;
        }
        for (; jb < n; jb += 32u) {
            unsigned int j = jb + lane;
            if (j < n) cnt += (keys[j] > kb);
        }
        cnt = __reduce_add_sync(0xFFFFFFFFu, cnt);
        if (lane == 0 && cnt < (unsigned int)T)
            write_det(cnt, kb, pb, ob, ocls, out, K, T, magic);
    }
}

// Grid barrier for the (never-taken) fallback path only.
__device__ __forceinline__ void grid_barrier(unsigned int nblocks) {
    __syncthreads();
    __threadfence();
    if (threadIdx.x == 0) {
        unsigned int old = atomicAdd(&g_bar, 1u);
        unsigned int target = (old / nblocks + 1u) * nblocks;
        while (atomicAdd(&g_bar, 0u) < target) __nanosleep(256);
    }
    __syncthreads();
}

// ---------------------------------------------------------------------------
// Kernel B: fast path = warp-per-item parallel rank straight from global keys.
// g_count read once per block (shared broadcast); the last-arrival reset
// happens EARLY (after the block-wide read), overlapping the ranking work.
// Fallback = exact hist -> cutoff -> collect -> rank (end-of-kernel reset).
// ---------------------------------------------------------------------------
__global__ void __launch_bounds__(256)
k_rank(const float4* __restrict__ hoi4,
       const float*  __restrict__ ps, const float* __restrict__ os,
       const float4* __restrict__ pb, const float4* __restrict__ ob,
       const int*    __restrict__ ocls, float* __restrict__ out,
       unsigned int nvec, unsigned int N, unsigned int K,
       unsigned long long magic, int T, unsigned int nblocks) {
    __shared__ unsigned int s_n;
    if (threadIdx.x == 0) s_n = *(volatile unsigned int*)&g_count;
    __syncthreads();
    unsigned int n = s_n;                                  // uniform across blocks
    bool fast = (n >= (unsigned int)T && n <= RANKMAX);

    if (fast) {
        // Early arrive+reset: every block has consumed n (syncthreads above)
        // before its arrival; the final arrival resets. Overlaps ranking.
        if (threadIdx.x == 0) {
            unsigned int old = atomicAdd(&g_done, 1u);
            if ((old % nblocks) == nblocks - 1u) g_count = 0;   // g_count2 already 0
        }
        warp_rank_write(g_ck, n, pb, ob, ocls, out, K, T, magic);
        return;
    }

    // ===== exact fallback (all blocks take this branch uniformly) =====
    __shared__ unsigned int sh[NBINS];
    {   // zero global hist
        unsigned int stride = gridDim.x * blockDim.x;
        for (unsigned int i = blockIdx.x * blockDim.x + threadIdx.x; i < NBINS; i += stride)
            g_hist[i] = 0;
    }
    grid_barrier(nblocks);

    {   // shared-privatized histogram of v > THRESH
        for (int i = threadIdx.x; i < NBINS; i += blockDim.x) sh[i] = 0;
        __syncthreads();
        unsigned int stride = gridDim.x * blockDim.x;
        for (unsigned int q = blockIdx.x * blockDim.x + threadIdx.x; q < nvec; q += stride) {
            float4 h = hoi4[q];
            unsigned int e = q * 4u;
            float hv[4] = {h.x, h.y, h.z, h.w};
            #pragma unroll
            for (int j = 0; j < 4; j++) {
                unsigned int idx = e + (unsigned)j;
                unsigned int r = (unsigned int)(((unsigned long long)idx * magic) >> 33);
                float v = hv[j] * ps[r] * os[r];
                if (v > THRESH) {
                    unsigned int b = (unsigned int)(v * (float)NBINS);
                    if (b > NBINS - 1) b = NBINS - 1;
                    atomicAdd(&sh[b], 1u);
                }
            }
        }
        if (blockIdx.x == 0 && threadIdx.x == 0) {
            for (unsigned int e = nvec * 4u; e < N; e++) {
                unsigned int r = (unsigned int)(((unsigned long long)e * magic) >> 33);
                float v = ((const float*)hoi4)[e] * ps[r] * os[r];
                if (v > THRESH) {
                    unsigned int b = (unsigned int)(v * (float)NBINS);
                    if (b > NBINS - 1) b = NBINS - 1;
                    atomicAdd(&sh[b], 1u);
                }
            }
        }
        __syncthreads();
        for (int i = threadIdx.x; i < NBINS; i += blockDim.x)
            if (sh[i]) atomicAdd(&g_hist[i], sh[i]);
    }
    grid_barrier(nblocks);

    __shared__ unsigned int s_cut;
    if (threadIdx.x == 0) {
        unsigned int cum = 0, cut = 0;
        for (int b = NBINS - 1; b >= 0; b--) {
            cum += g_hist[b];
            if (cum >= (unsigned int)T) { cut = (unsigned int)b; break; }
        }
        s_cut = cut;
    }
    __syncthreads();
    unsigned int cut = s_cut;

    {   // collect candidates with bin >= cutoff (packed keys)
        unsigned int stride = gridDim.x * blockDim.x;
        for (unsigned int q = blockIdx.x * blockDim.x + threadIdx.x; q < nvec; q += stride) {
            float4 h = hoi4[q];
            unsigned int e = q * 4u;
            float hv[4] = {h.x, h.y, h.z, h.w};
            #pragma unroll
            for (int j = 0; j < 4; j++) {
                unsigned int idx = e + (unsigned)j;
                unsigned int r = (unsigned int)(((unsigned long long)idx * magic) >> 33);
                float v = hv[j] * ps[r] * os[r];
                if (v > THRESH) {
                    unsigned int b = (unsigned int)(v * (float)NBINS);
                    if (b > NBINS - 1) b = NBINS - 1;
                    if (b >= cut) {
                        unsigned int pos = atomicAdd(&g_count2, 1u);
                        if (pos < CAP)
                            g_ck2[pos] = mk_key(__float_as_uint(v), idx);
                    }
                }
            }
        }
        if (blockIdx.x == 0 && threadIdx.x == 0) {
            for (unsigned int e = nvec * 4u; e < N; e++) {
                unsigned int r = (unsigned int)(((unsigned long long)e * magic) >> 33);
                float v = ((const float*)hoi4)[e] * ps[r] * os[r];
                if (v > THRESH) {
                    unsigned int b = (unsigned int)(v * (float)NBINS);
                    if (b > NBINS - 1) b = NBINS - 1;
                    if (b >= cut) {
                        unsigned int pos = atomicAdd(&g_count2, 1u);
                        if (pos < CAP)
                            g_ck2[pos] = mk_key(__float_as_uint(v), e);
                    }
                }
            }
        }
    }
    grid_barrier(nblocks);

    unsigned int n2 = *(volatile unsigned int*)&g_count2;
    if (n2 > CAP) n2 = CAP;
    warp_rank_write(g_ck2, n2, pb, ob, ocls, out, K, T, magic);

    // zero-pad unfilled slots (n2 < T): block 0
    if (blockIdx.x == 0) {
        for (int s = threadIdx.x; s < T; s += blockDim.x) {
            if ((unsigned int)s >= n2) {
                out[s] = 0.0f;
                #pragma unroll
                for (int d = 0; d < 4; d++) {
                    out[T + 4 * s + d] = 0.0f;
                    out[5 * T + 4 * s + d] = 0.0f;
                }
                out[9 * T + s] = 0.0f;
                out[10 * T + s] = 0.0f;
                out[11 * T + s] = 0.0f;
            }
        }
    }

    // fallback: last-block-out reset of both counters
    __syncthreads();
    __threadfence();
    if (threadIdx.x == 0) {
        unsigned int old = atomicAdd(&g_done, 1u);
        if ((old % nblocks) == nblocks - 1u) {
            g_count = 0;
            g_count2 = 0;
        }
    }
}

// ---------------------------------------------------------------------------
extern "C" void kernel_launch(void* const* d_in, const int* in_sizes, int n_in,
                              void* d_out, int out_size) {
    const float* pb   = (const float*)d_in[0];
    const float* ob   = (const float*)d_in[1];
    const float* ps   = (const float*)d_in[2];
    const float* os   = (const float*)d_in[3];
    const int*   ocls = (const int*)d_in[4];
    const float* hoi  = (const float*)d_in[5];

    int R = in_sizes[2];
    unsigned int N = (unsigned int)in_sizes[5];
    unsigned int K = N / (unsigned int)R;
    int T = out_size / 12;
    unsigned int nvec = N / 4u;
    unsigned long long magic = ((1ULL << 33) + K - 1) / K;  // exact e/K, e < 2^33/K

    int dev = 0, sms = 148;
    cudaGetDevice(&dev);
    cudaDeviceGetAttribute(&sms, cudaDevAttrMultiProcessorCount, dev);

    unsigned int scan_blocks = (unsigned int)(sms * 8);
    k_scan<<<scan_blocks, 256>>>((const float4*)hoi, ps, os, nvec, N, K, magic);

    unsigned int fb_blocks = (unsigned int)sms;   // co-resident for fallback barrier
    k_rank<<<fb_blocks, 256>>>((const float4*)hoi, ps, os,
                               (const float4*)pb, (const float4*)ob, ocls,
                               (float*)d_out, nvec, N, K, magic, T, fb_blocks);
}